// round 7
// baseline (speedup 1.0000x reference)
#include <cuda_runtime.h>
#include <cuda_bf16.h>
#include <cstdint>
#include <math.h>

// HungarianMatcher cost matrix, fused single kernel (v6b: TMA bulk store).
//   u = head_q - head_t,  v = tip_q - tip_t   (packed f32x2 diffs)
//   C = 5*(|ux|+|uy|+|vx|+|vy|) + 2.5*(|wx|+|wy|) + cls[label_t],  w = u+v
//
// v6: each block computes its full QT x T tile into dynamic smem (STS.128),
// then ONE cp.async.bulk (1-D, no tensormap) streams the tile to gmem --
// the tile is contiguous because blocks own whole query rows. This removes
// the STG.128 issue cost (12 cyc each) and the L1tex per-thread store wall.
// Fallback kernel with STG.128 for shapes where the tile exceeds smem.

#define QT 8          // queries per block
#define TPT 4         // targets per thread
#define MAXNC 16

typedef unsigned long long u64;
typedef unsigned int u32;

__device__ __forceinline__ u64 pk2(float lo, float hi) {
    u64 r; asm("mov.b64 %0, {%1, %2};" : "=l"(r) : "f"(lo), "f"(hi)); return r;
}
__device__ __forceinline__ void upk2(u64 v, float& lo, float& hi) {
    asm("mov.b64 {%0, %1}, %2;" : "=f"(lo), "=f"(hi) : "l"(v));
}
__device__ __forceinline__ u64 addx2(u64 a, u64 b) {
    u64 r; asm("add.rn.f32x2 %0, %1, %2;" : "=l"(r) : "l"(a), "l"(b)); return r;
}
__device__ __forceinline__ u64 mulx2(u64 a, u64 b) {
    u64 r; asm("mul.rn.f32x2 %0, %1, %2;" : "=l"(r) : "l"(a), "l"(b)); return r;
}

// ---- shared prologue: class costs + query staging + target regs ----
struct Tgt { u64 nth[TPT], ntt[TPT]; bool lsel[TPT]; };

__device__ __forceinline__ void prologue(const float* __restrict__ logits,
                                         const float* __restrict__ pscrews,
                                         const int*   __restrict__ tlabels,
                                         const float* __restrict__ tscrews,
                                         float* s_cls, float* s_q,
                                         int qbase, int N, int nc, int T,
                                         int& t0, Tgt& tg) {
    int k = threadIdx.x;
    if (k < QT * 4) {
        int q = qbase + (k >> 2);
        s_q[k] = (q < N) ? pscrews[(long long)q * 4 + (k & 3)] : 0.0f;
    }
    if (k >= 32 && k < 32 + QT * nc) {
        int kk = k - 32;
        int q = qbase + kk / nc;
        int c = kk % nc;
        float cost = 0.0f;
        if (q < N) {
            float l = logits[(long long)q * nc + c];
            float p = 1.0f / (1.0f + expf(-l));
            float pos = (1.0f - p) * (1.0f - p) * (-logf(p + 1e-8f));
            float neg = p * p * (-log1pf(-(p - 1e-8f)));
            cost = 2.0f * (pos - neg);
        }
        s_cls[kk] = cost;
    }
    const u64 NEG1 = 0xBF800000BF800000ULL;
    t0 = threadIdx.x * TPT;
    if (t0 > T - TPT) t0 = T - TPT;          // clamp (requires T >= TPT)
    #pragma unroll
    for (int j = 0; j < TPT; j++) {
        int tj = t0 + j;
        float4 s = reinterpret_cast<const float4*>(tscrews)[tj];
        tg.nth[j] = mulx2(pk2(s.x, s.y), NEG1);
        tg.ntt[j] = mulx2(pk2(s.z, s.w), NEG1);
        tg.lsel[j] = (tlabels[tj] != 0);
    }
}

__device__ __forceinline__ float4 compute4(u64 qh2, u64 qt2, float c0, float c1,
                                           const Tgt& tg) {
    float r[TPT];
    #pragma unroll
    for (int j = 0; j < TPT; j++) {
        u64 u = addx2(qh2, tg.nth[j]);
        u64 v = addx2(qt2, tg.ntt[j]);
        u64 w = addx2(u, v);
        float ux, uy, vx, vy, wx, wy;
        upk2(u, ux, uy); upk2(v, vx, vy); upk2(w, wx, wy);
        float s1 = fabsf(ux) + fabsf(uy);
        float s2 = fabsf(vx) + fabsf(vy);
        float s3 = fabsf(wx) + fabsf(wy);
        float cls = tg.lsel[j] ? c1 : c0;
        r[j] = fmaf(5.0f, s1 + s2, fmaf(2.5f, s3, cls));
    }
    float4 vv; vv.x = r[0]; vv.y = r[1]; vv.z = r[2]; vv.w = r[3];
    return vv;
}

// ================= v6: smem tile + TMA bulk store =================
__global__ __launch_bounds__(256)
void matcher_tma(const float* __restrict__ logits,
                 const float* __restrict__ pscrews,
                 const int*   __restrict__ tlabels,
                 const float* __restrict__ tscrews,
                 float* __restrict__ out,
                 int N, int nc, int T) {
    __shared__ float s_cls[QT * MAXNC];
    __shared__ float s_q[QT * 4];
    extern __shared__ float s_tile[];        // QT * T floats

    int qbase = blockIdx.x * QT;
    int t0; Tgt tg;
    prologue(logits, pscrews, tlabels, tscrews, s_cls, s_q, qbase, N, nc, T, t0, tg);
    __syncthreads();

    int qmax = min(QT, N - qbase);
    #pragma unroll
    for (int q = 0; q < QT; q++) {
        if (q >= qmax) break;
        float4 qs = reinterpret_cast<const float4*>(s_q)[q];
        u64 qh2 = pk2(qs.x, qs.y);
        u64 qt2 = pk2(qs.z, qs.w);
        float c0 = s_cls[q * nc + 0];
        float c1 = (nc > 1) ? s_cls[q * nc + 1] : c0;
        float4 vv = compute4(qh2, qt2, c0, c1, tg);
        // conflict-free STS.128 (clamped threads rewrite identical data)
        *reinterpret_cast<float4*>(s_tile + q * T + t0) = vv;
    }
    __syncthreads();

    if (threadIdx.x == 0) {
        asm volatile("fence.proxy.async.shared::cta;" ::: "memory");
        u32 src;
        asm("{ .reg .u64 t; cvta.to.shared.u64 t, %1; cvt.u32.u64 %0, t; }"
            : "=r"(src) : "l"(s_tile));
        float* dst = out + (long long)qbase * T;
        u32 bytes = (u32)(qmax * T) * 4u;
        asm volatile("cp.async.bulk.global.shared::cta.bulk_group [%0], [%1], %2;"
                     :: "l"(dst), "r"(src), "r"(bytes) : "memory");
        asm volatile("cp.async.bulk.commit_group;" ::: "memory");
        asm volatile("cp.async.bulk.wait_group.read 0;" ::: "memory");
    }
}

// ================= fallback: direct STG.128 (v5 path) =================
__global__ __launch_bounds__(256)
void matcher_stg(const float* __restrict__ logits,
                 const float* __restrict__ pscrews,
                 const int*   __restrict__ tlabels,
                 const float* __restrict__ tscrews,
                 float* __restrict__ out,
                 int N, int nc, int T) {
    __shared__ float s_cls[QT * MAXNC];
    __shared__ float s_q[QT * 4];

    int qbase = blockIdx.x * QT;
    int t0; Tgt tg;
    prologue(logits, pscrews, tlabels, tscrews, s_cls, s_q, qbase, N, nc, T, t0, tg);
    __syncthreads();

    int qmax = N - qbase;
    float* ptr = out + (long long)qbase * T + t0;
    #pragma unroll
    for (int q = 0; q < QT; q++) {
        if (q >= qmax) break;
        float4 qs = reinterpret_cast<const float4*>(s_q)[q];
        u64 qh2 = pk2(qs.x, qs.y);
        u64 qt2 = pk2(qs.z, qs.w);
        float c0 = s_cls[q * nc + 0];
        float c1 = (nc > 1) ? s_cls[q * nc + 1] : c0;
        float4 vv = compute4(qh2, qt2, c0, c1, tg);
        __stcs(reinterpret_cast<float4*>(ptr), vv);
        ptr += T;
    }
}

extern "C" void kernel_launch(void* const* d_in, const int* in_sizes, int n_in,
                              void* d_out, int out_size) {
    const float* logits  = (const float*)d_in[0];   // [bs, nq, nc]
    const float* pscrews = (const float*)d_in[1];   // [bs, nq, 4]
    const int*   tlabels = (const int*)d_in[2];     // [T]
    const float* tscrews = (const float*)d_in[3];   // [T, 4]
    // d_in[4] (num_targets_per_image) does not affect the flat [N, T] output.

    int N  = in_sizes[1] / 4;          // bs * nq
    int nc = in_sizes[0] / N;          // 2
    int T  = in_sizes[2];              // total targets
    float* out = (float*)d_out;

    int need = (T + TPT - 1) / TPT;
    int tpb = need > 256 ? ((need + 31) & ~31) : 256;
    if (tpb > 1024) tpb = 1024;

    int blocks = (N + QT - 1) / QT;
    size_t tile_bytes = (size_t)QT * T * sizeof(float);

    // TMA path needs: tile fits in default dyn-smem, 16B-aligned rows.
    if (tile_bytes <= 46 * 1024 && (T % 4) == 0 && T >= TPT) {
        matcher_tma<<<blocks, tpb, tile_bytes>>>(logits, pscrews, tlabels,
                                                 tscrews, out, N, nc, T);
    } else {
        matcher_stg<<<blocks, tpb>>>(logits, pscrews, tlabels,
                                     tscrews, out, N, nc, T);
    }
}

// round 8
// speedup vs baseline: 1.0795x; 1.0795x over previous
#include <cuda_runtime.h>
#include <cuda_bf16.h>
#include <cstdint>
#include <math.h>

// HungarianMatcher cost matrix (v7: persistent blocks, direct STG.128).
//   u = head_q - head_t,  v = tip_q - tip_t   (packed f32x2 diffs)
//   C = 5*(|ux|+|uy|+|vx|+|vy|) + 2.5*(|wx|+|wy|) + cls[label_t],  w = u+v
//
// v7: grid is sized to exactly fill the chip (148 SMs x 6 CTAs); each block
// loads its TPT targets into registers ONCE, then loops over query tiles.
// Kills wave-transition overhead (5 waves -> 1) and repeated prologues.
// Stores stay direct STG.128 (R7 showed smem+TMA doubles L1-complex traffic).

#define QT 8          // queries per tile
#define TPT 4         // targets per thread
#define MAXNC 16
#define NSM 148
#define CTAS_PER_SM 6

typedef unsigned long long u64;

__device__ __forceinline__ u64 pk2(float lo, float hi) {
    u64 r; asm("mov.b64 %0, {%1, %2};" : "=l"(r) : "f"(lo), "f"(hi)); return r;
}
__device__ __forceinline__ void upk2(u64 v, float& lo, float& hi) {
    asm("mov.b64 {%0, %1}, %2;" : "=f"(lo), "=f"(hi) : "l"(v));
}
__device__ __forceinline__ u64 addx2(u64 a, u64 b) {
    u64 r; asm("add.rn.f32x2 %0, %1, %2;" : "=l"(r) : "l"(a), "l"(b)); return r;
}
__device__ __forceinline__ u64 mulx2(u64 a, u64 b) {
    u64 r; asm("mul.rn.f32x2 %0, %1, %2;" : "=l"(r) : "l"(a), "l"(b)); return r;
}

__global__ __launch_bounds__(256)
void matcher_persist(const float* __restrict__ logits,
                     const float* __restrict__ pscrews,
                     const int*   __restrict__ tlabels,
                     const float* __restrict__ tscrews,
                     float* __restrict__ out,
                     int N, int nc, int T, int ntiles) {
    __shared__ float s_cls[QT * MAXNC];
    __shared__ float s_q[QT * 4];

    int k = threadIdx.x;

    // ---- targets: loaded ONCE per block, live in registers for all tiles
    const u64 NEG1 = 0xBF800000BF800000ULL;
    int t0 = k * TPT;
    if (t0 > T - TPT) t0 = T - TPT;          // clamp (requires T >= TPT)

    u64 nth[TPT], ntt[TPT];
    bool lsel[TPT];
    #pragma unroll
    for (int j = 0; j < TPT; j++) {
        int tj = t0 + j;
        float4 s = reinterpret_cast<const float4*>(tscrews)[tj];
        nth[j] = mulx2(pk2(s.x, s.y), NEG1);
        ntt[j] = mulx2(pk2(s.z, s.w), NEG1);
        lsel[j] = (tlabels[tj] != 0);
    }

    // ---- persistent tile loop
    for (int tile = blockIdx.x; tile < ntiles; tile += gridDim.x) {
        int qbase = tile * QT;

        __syncthreads();   // previous tile's reads of s_q/s_cls are done
        if (k < QT * 4) {
            int q = qbase + (k >> 2);
            s_q[k] = (q < N) ? pscrews[(long long)q * 4 + (k & 3)] : 0.0f;
        }
        if (k >= 32 && k < 32 + QT * nc) {
            int kk = k - 32;
            int q = qbase + kk / nc;
            int c = kk % nc;
            float cost = 0.0f;
            if (q < N) {
                float l = logits[(long long)q * nc + c];
                float p = 1.0f / (1.0f + expf(-l));
                float pos = (1.0f - p) * (1.0f - p) * (-logf(p + 1e-8f));
                float neg = p * p * (-log1pf(-(p - 1e-8f)));
                cost = 2.0f * (pos - neg);
            }
            s_cls[kk] = cost;
        }
        __syncthreads();

        int qmax = N - qbase;                 // >=1
        float* ptr = out + (long long)qbase * T + t0;

        #pragma unroll
        for (int q = 0; q < QT; q++) {
            if (q >= qmax) break;
            float4 qs = reinterpret_cast<const float4*>(s_q)[q];  // LDS.128 bcast
            u64 qh2 = pk2(qs.x, qs.y);
            u64 qt2 = pk2(qs.z, qs.w);
            float c0 = s_cls[q * nc + 0];
            float c1 = (nc > 1) ? s_cls[q * nc + 1] : c0;

            float r[TPT];
            #pragma unroll
            for (int j = 0; j < TPT; j++) {
                u64 u = addx2(qh2, nth[j]);
                u64 v = addx2(qt2, ntt[j]);
                u64 w = addx2(u, v);
                float ux, uy, vx, vy, wx, wy;
                upk2(u, ux, uy); upk2(v, vx, vy); upk2(w, wx, wy);
                float s1 = fabsf(ux) + fabsf(uy);   // FADD |a|,|b|
                float s2 = fabsf(vx) + fabsf(vy);
                float s3 = fabsf(wx) + fabsf(wy);
                float cls = lsel[j] ? c1 : c0;
                r[j] = fmaf(5.0f, s1 + s2, fmaf(2.5f, s3, cls));
            }

            float4 vv; vv.x = r[0]; vv.y = r[1]; vv.z = r[2]; vv.w = r[3];
            __stcs(reinterpret_cast<float4*>(ptr), vv);
            ptr += T;
        }
    }
}

extern "C" void kernel_launch(void* const* d_in, const int* in_sizes, int n_in,
                              void* d_out, int out_size) {
    const float* logits  = (const float*)d_in[0];   // [bs, nq, nc]
    const float* pscrews = (const float*)d_in[1];   // [bs, nq, 4]
    const int*   tlabels = (const int*)d_in[2];     // [T]
    const float* tscrews = (const float*)d_in[3];   // [T, 4]
    // d_in[4] (num_targets_per_image) does not affect the flat [N, T] output.

    int N  = in_sizes[1] / 4;          // bs * nq
    int nc = in_sizes[0] / N;          // 2
    int T  = in_sizes[2];              // total targets
    float* out = (float*)d_out;

    int need = (T + TPT - 1) / TPT;    // threads to cover T
    int tpb = need > 256 ? ((need + 31) & ~31) : 256;
    if (tpb > 1024) tpb = 1024;

    int ntiles = (N + QT - 1) / QT;
    int nblocks = NSM * CTAS_PER_SM;
    if (nblocks > ntiles) nblocks = ntiles;

    matcher_persist<<<nblocks, tpb>>>(logits, pscrews, tlabels, tscrews,
                                      out, N, nc, T, ntiles);
}